// round 3
// baseline (speedup 1.0000x reference)
#include <cuda_runtime.h>
#include <cstddef>

#define BB 4096
#define LL 50
#define NN 50
#define DD 128

// Shared memory layout (floats unless noted):
//   nodes_s : NN*DD            = 6400
//   w_s     : DD*DD            = 16384   (W_last, then overwritten by W_seq)
//   vnp_s   : 2*DD             = 256     (k-split partials of v_n @ W_last)
//   alpha_s : NN               = 50
//   part    : 2*4*25           = 200     (per-half, per-warp alpha partials)
//   cnt_s   : NN ints          = 50
//   meta    : 2 ints                     (seq_len, last_idx)
#define SM_NODES   0
#define SM_W       (NN*DD)
#define SM_VNP     (SM_W + DD*DD)
#define SM_ALPHA   (SM_VNP + 2*DD)
#define SM_PART    (SM_ALPHA + NN)
#define SM_CNT     (SM_PART + 200)
#define SM_META    (SM_CNT + NN)
#define SM_FLOATS  (SM_META + 2)
#define SMEM_BYTES (SM_FLOATS * 4)

__global__ __launch_bounds__(256, 2)
void session_graph_kernel(
    const int*   __restrict__ seq,      // [B, L]
    const int*   __restrict__ mask,     // [B, L]
    const float* __restrict__ nodes,    // [B, N, D]
    const float* __restrict__ W_last,   // [D, D]
    const float* __restrict__ W_seq,    // [D, D]
    const float* __restrict__ b_seq,    // [D]
    const float* __restrict__ W_alpha,  // [D]
    float*       __restrict__ out)      // [B*D] v_n, then [B*D] session_graph
{
    extern __shared__ float sm[];
    float* nodes_s = sm + SM_NODES;
    float* w_s     = sm + SM_W;
    float* vnp_s   = sm + SM_VNP;
    float* alpha_s = sm + SM_ALPHA;
    float* part    = sm + SM_PART;
    int*   cnt_s   = (int*)(sm + SM_CNT);
    int*   meta    = (int*)(sm + SM_META);

    const int tid  = threadIdx.x;
    const int b    = blockIdx.x;
    const int col  = tid & (DD - 1);
    const int half = tid >> 7;           // 0 or 1
    const int wh   = (tid >> 5) & 3;     // warp index within half (0..3)
    const int lane = tid & 31;

    if (tid < NN) { cnt_s[tid] = 0; }
    if (tid == 0) { meta[0] = 0; }
    __syncthreads();

    // --- masked node counts + sequence length ---
    if (tid < LL) {
        int m  = mask[b * LL + tid];
        int ix = seq[b * LL + tid];
        if (m) {
            atomicAdd(&cnt_s[ix], 1);
            atomicAdd(&meta[0], 1);
        }
    }

    // --- load node tile [N, D] into smem ---
    {
        const float4* nv4 = (const float4*)(nodes + (size_t)b * NN * DD);
        float4* ns4 = (float4*)nodes_s;
        #pragma unroll
        for (int i = tid; i < NN * DD / 4; i += 256) ns4[i] = nv4[i];
    }
    // --- load W_last into w_s ---
    {
        const float4* wl4 = (const float4*)W_last;
        float4* ws4 = (float4*)w_s;
        #pragma unroll
        for (int i = tid; i < DD * DD / 4; i += 256) ws4[i] = wl4[i];
    }
    __syncthreads();

    if (tid == 0) {
        int len = meta[0];
        int li  = (len > 0) ? seq[b * LL + len - 1] : seq[b * LL + LL - 1];
        meta[1] = li;
    }
    __syncthreads();
    const int last = meta[1];

    // --- vn_proj partial: half h covers k in [h*64, h*64+64) ---
    {
        float acc = 0.f;
        const int k0 = half * 64;
        const float* vr = nodes_s + last * DD + k0;
        const float* wr = w_s + k0 * DD + col;
        #pragma unroll 16
        for (int k = 0; k < 64; k++) {
            acc = fmaf(vr[k], wr[k * DD], acc);
        }
        vnp_s[half * DD + col] = acc;
    }
    __syncthreads();

    // --- overwrite w_s with W_seq ---
    {
        const float4* wq4 = (const float4*)W_seq;
        float4* ws4 = (float4*)w_s;
        #pragma unroll
        for (int i = tid; i < DD * DD / 4; i += 256) ws4[i] = wq4[i];
    }
    __syncthreads();

    const float vnp = vnp_s[col] + vnp_s[DD + col] + b_seq[col];
    const float wa  = W_alpha[col];

    // --- node_proj GEMM + sigmoid + alpha partials ---
    // this half owns nodes [half*25, half*25+25), processed in 5 groups of 5
    for (int g = 0; g < 5; g++) {
        const int nb = half * 25 + g * 5;
        float a0 = 0.f, a1 = 0.f, a2 = 0.f, a3 = 0.f, a4 = 0.f;
        const float4* r0 = (const float4*)(nodes_s + (nb + 0) * DD);
        const float4* r1 = (const float4*)(nodes_s + (nb + 1) * DD);
        const float4* r2 = (const float4*)(nodes_s + (nb + 2) * DD);
        const float4* r3 = (const float4*)(nodes_s + (nb + 3) * DD);
        const float4* r4 = (const float4*)(nodes_s + (nb + 4) * DD);
        const float* wp = w_s + col;
        #pragma unroll 8
        for (int k4 = 0; k4 < 32; k4++) {
            const float w0 = wp[(k4 * 4 + 0) * DD];
            const float w1 = wp[(k4 * 4 + 1) * DD];
            const float w2 = wp[(k4 * 4 + 2) * DD];
            const float w3 = wp[(k4 * 4 + 3) * DD];
            float4 x;
            x = r0[k4]; a0 = fmaf(x.x,w0,a0); a0 = fmaf(x.y,w1,a0); a0 = fmaf(x.z,w2,a0); a0 = fmaf(x.w,w3,a0);
            x = r1[k4]; a1 = fmaf(x.x,w0,a1); a1 = fmaf(x.y,w1,a1); a1 = fmaf(x.z,w2,a1); a1 = fmaf(x.w,w3,a1);
            x = r2[k4]; a2 = fmaf(x.x,w0,a2); a2 = fmaf(x.y,w1,a2); a2 = fmaf(x.z,w2,a2); a2 = fmaf(x.w,w3,a2);
            x = r3[k4]; a3 = fmaf(x.x,w0,a3); a3 = fmaf(x.y,w1,a3); a3 = fmaf(x.z,w2,a3); a3 = fmaf(x.w,w3,a3);
            x = r4[k4]; a4 = fmaf(x.x,w0,a4); a4 = fmaf(x.y,w1,a4); a4 = fmaf(x.z,w2,a4); a4 = fmaf(x.w,w3,a4);
        }
        float acc[5] = {a0, a1, a2, a3, a4};
        #pragma unroll
        for (int r = 0; r < 5; r++) {
            const float z = vnp + acc[r];
            const float s = 1.0f / (1.0f + expf(-z));
            float p = s * wa;
            // warp reduce over the 32 cols this warp holds
            #pragma unroll
            for (int off = 16; off > 0; off >>= 1)
                p += __shfl_xor_sync(0xffffffffu, p, off);
            if (lane == 0)
                part[half * 100 + wh * 25 + g * 5 + r] = p;
        }
    }
    __syncthreads();

    // deterministic combine: alpha[n] = sum over 4 warps of that half's partials
    if (tid < NN) {
        const int h = tid / 25;
        const int w0 = tid % 25;
        alpha_s[tid] = part[h * 100 + 0 * 25 + w0]
                     + part[h * 100 + 1 * 25 + w0]
                     + part[h * 100 + 2 * 25 + w0]
                     + part[h * 100 + 3 * 25 + w0];
    }
    __syncthreads();

    // --- outputs ---
    if (half == 1) {
        // v_n
        out[(size_t)b * DD + col] = nodes_s[last * DD + col];
    } else {
        // session_graph[b, col] = sum_n cnt[n] * alpha[n] * nodes[n, col]
        float sg = 0.f;
        #pragma unroll
        for (int n = 0; n < NN; n++) {
            const float ca = (float)cnt_s[n] * alpha_s[n];
            sg = fmaf(ca, nodes_s[n * DD + col], sg);
        }
        out[(size_t)BB * DD + (size_t)b * DD + col] = sg;
    }
}

extern "C" void kernel_launch(void* const* d_in, const int* in_sizes, int n_in,
                              void* d_out, int out_size) {
    const int*   seq     = (const int*)  d_in[0];
    const int*   mask    = (const int*)  d_in[1];
    const float* nodes   = (const float*)d_in[2];
    // d_in[3] = batch_size (scalar), unused — shapes are compile-time constants
    const float* W_last  = (const float*)d_in[4];
    const float* W_seq   = (const float*)d_in[5];
    const float* b_seq   = (const float*)d_in[6];
    const float* W_alpha = (const float*)d_in[7];
    float* out = (float*)d_out;

    cudaFuncSetAttribute(session_graph_kernel,
                         cudaFuncAttributeMaxDynamicSharedMemorySize, SMEM_BYTES);
    session_graph_kernel<<<BB, 256, SMEM_BYTES>>>(
        seq, mask, nodes, W_last, W_seq, b_seq, W_alpha, out);
}

// round 4
// speedup vs baseline: 1.1296x; 1.1296x over previous
#include <cuda_runtime.h>
#include <cstddef>

#define BB 4096
#define LL 50
#define NN 50
#define DD 128

// scratch: vn_proj (+ b_seq) per batch
__device__ float g_vnp[BB * DD];

// ============================================================
// Kernel A: per-batch last index, v_n output, vnp = v_n@W_last + b_seq
// ============================================================
__global__ __launch_bounds__(128)
void vn_kernel(
    const int*   __restrict__ seq,     // [B, L]
    const int*   __restrict__ mask,    // [B, L]
    const float* __restrict__ nodes,   // [B, N, D]
    const float* __restrict__ W_last,  // [D, D]
    const float* __restrict__ b_seq,   // [D]
    float*       __restrict__ out)     // v_n at out[0 : B*D]
{
    __shared__ float vn_s[DD];
    __shared__ int   meta[2];   // [0]=len accumulator, [1]=last idx

    const int tid = threadIdx.x;
    const int b   = blockIdx.x;

    if (tid == 0) meta[0] = 0;
    __syncthreads();
    if (tid < LL) {
        if (mask[b * LL + tid]) atomicAdd(&meta[0], 1);
    }
    __syncthreads();
    if (tid == 0) {
        int len = meta[0];
        meta[1] = (len > 0) ? seq[b * LL + len - 1] : seq[b * LL + LL - 1];
    }
    __syncthreads();
    const int last = meta[1];

    // load v_n, write it to output
    const float v = nodes[(size_t)b * NN * DD + (size_t)last * DD + tid];
    vn_s[tid] = v;
    out[(size_t)b * DD + tid] = v;
    __syncthreads();

    // vnp[col] = sum_k v_n[k] * W_last[k, col]  (+ b_seq)
    float a0 = 0.f, a1 = 0.f, a2 = 0.f, a3 = 0.f;
    const float* wp = W_last + tid;
    #pragma unroll 8
    for (int k = 0; k < DD; k += 4) {
        a0 = fmaf(vn_s[k + 0], wp[(k + 0) * DD], a0);
        a1 = fmaf(vn_s[k + 1], wp[(k + 1) * DD], a1);
        a2 = fmaf(vn_s[k + 2], wp[(k + 2) * DD], a2);
        a3 = fmaf(vn_s[k + 3], wp[(k + 3) * DD], a3);
    }
    g_vnp[(size_t)b * DD + tid] = (a0 + a1) + (a2 + a3) + b_seq[tid];
}

// ============================================================
// Main kernel: node_proj GEMM (M=25 per half), alpha, session_graph
// ============================================================
// Shared memory layout (floats unless noted):
//   nodes_s : NN*DD = 6400
//   w_s     : DD*DD = 16384   (W_seq)
//   part    : 2*4*25 = 200
//   alpha_s : NN = 50         (final: cnt*alpha)
//   cnt_s   : NN ints = 50
#define SM_NODES   0
#define SM_W       (NN*DD)
#define SM_PART    (SM_W + DD*DD)
#define SM_ALPHA   (SM_PART + 200)
#define SM_CNT     (SM_ALPHA + NN)
#define SM_FLOATS  (SM_CNT + NN)
#define SMEM_BYTES (SM_FLOATS * 4)

__global__ __launch_bounds__(256, 2)
void session_graph_kernel(
    const int*   __restrict__ seq,      // [B, L]
    const int*   __restrict__ mask,     // [B, L]
    const float* __restrict__ nodes,    // [B, N, D]
    const float* __restrict__ W_seq,    // [D, D]
    const float* __restrict__ W_alpha,  // [D]
    float*       __restrict__ out)      // session_graph at out[B*D : 2*B*D]
{
    extern __shared__ float sm[];
    float* nodes_s = sm + SM_NODES;
    float* w_s     = sm + SM_W;
    float* part    = sm + SM_PART;
    float* alpha_s = sm + SM_ALPHA;
    int*   cnt_s   = (int*)(sm + SM_CNT);

    const int tid  = threadIdx.x;
    const int b    = blockIdx.x;
    const int col  = tid & (DD - 1);
    const int half = tid >> 7;           // 0 or 1
    const int wh   = (tid >> 5) & 3;     // warp index within half
    const int lane = tid & 31;

    if (tid < NN) cnt_s[tid] = 0;
    __syncthreads();

    // masked node multiplicities
    if (tid < LL) {
        if (mask[b * LL + tid]) atomicAdd(&cnt_s[seq[b * LL + tid]], 1);
    }

    // stage node tile and W_seq into smem
    {
        const float4* nv4 = (const float4*)(nodes + (size_t)b * NN * DD);
        float4* ns4 = (float4*)nodes_s;
        #pragma unroll
        for (int i = tid; i < NN * DD / 4; i += 256) ns4[i] = nv4[i];
        const float4* wq4 = (const float4*)W_seq;
        float4* ws4 = (float4*)w_s;
        #pragma unroll
        for (int i = tid; i < DD * DD / 4; i += 256) ws4[i] = wq4[i];
    }

    const float vnp = g_vnp[(size_t)b * DD + col];
    const float wa  = W_alpha[col];
    __syncthreads();

    // --- node_proj GEMM: this half owns 25 nodes, 25 accumulators ---
    float acc[25];
    #pragma unroll
    for (int r = 0; r < 25; r++) acc[r] = 0.f;

    {
        const float*  wp  = w_s + col;
        const float4* nb4 = (const float4*)(nodes_s + half * 25 * DD);
        #pragma unroll 2
        for (int k4 = 0; k4 < 32; k4++) {
            const float w0 = wp[(k4 * 4 + 0) * DD];
            const float w1 = wp[(k4 * 4 + 1) * DD];
            const float w2 = wp[(k4 * 4 + 2) * DD];
            const float w3 = wp[(k4 * 4 + 3) * DD];
            #pragma unroll
            for (int r = 0; r < 25; r++) {
                const float4 x = nb4[r * (DD / 4) + k4];   // broadcast
                float a = acc[r];
                a = fmaf(x.x, w0, a);
                a = fmaf(x.y, w1, a);
                a = fmaf(x.z, w2, a);
                a = fmaf(x.w, w3, a);
                acc[r] = a;
            }
        }
    }

    // --- sigmoid, scale by W_alpha[col], cross-column reduce ---
    #pragma unroll
    for (int r = 0; r < 25; r++) {
        const float z = vnp + acc[r];
        const float s = 1.0f / (1.0f + expf(-z));
        float p = s * wa;
        #pragma unroll
        for (int off = 16; off > 0; off >>= 1)
            p += __shfl_xor_sync(0xffffffffu, p, off);
        if (lane == 0)
            part[half * 100 + wh * 25 + r] = p;
    }
    __syncthreads();

    // deterministic combine + fold in multiplicity: alpha_s[n] = cnt[n]*alpha[n]
    if (tid < NN) {
        const int h  = tid / 25;
        const int w0 = tid % 25;
        const float a = part[h * 100 +  0 + w0]
                      + part[h * 100 + 25 + w0]
                      + part[h * 100 + 50 + w0]
                      + part[h * 100 + 75 + w0];
        alpha_s[tid] = a * (float)cnt_s[tid];
    }
    __syncthreads();

    // --- session_graph[b, col] = sum_n (cnt*alpha)[n] * nodes[n, col] ---
    if (half == 0) {
        float sg = 0.f;
        #pragma unroll
        for (int n = 0; n < NN; n++)
            sg = fmaf(alpha_s[n], nodes_s[n * DD + col], sg);
        out[(size_t)BB * DD + (size_t)b * DD + col] = sg;
    }
}

extern "C" void kernel_launch(void* const* d_in, const int* in_sizes, int n_in,
                              void* d_out, int out_size) {
    const int*   seq     = (const int*)  d_in[0];
    const int*   mask    = (const int*)  d_in[1];
    const float* nodes   = (const float*)d_in[2];
    // d_in[3] = batch_size scalar (unused; compile-time constants)
    const float* W_last  = (const float*)d_in[4];
    const float* W_seq   = (const float*)d_in[5];
    const float* b_seq   = (const float*)d_in[6];
    const float* W_alpha = (const float*)d_in[7];
    float* out = (float*)d_out;

    vn_kernel<<<BB, 128>>>(seq, mask, nodes, W_last, b_seq, out);

    cudaFuncSetAttribute(session_graph_kernel,
                         cudaFuncAttributeMaxDynamicSharedMemorySize, SMEM_BYTES);
    session_graph_kernel<<<BB, 256, SMEM_BYTES>>>(
        seq, mask, nodes, W_seq, W_alpha, out);
}

// round 9
// speedup vs baseline: 1.6564x; 1.4663x over previous
#include <cuda_runtime.h>
#include <cuda_bf16.h>
#include <cstdint>
#include <cstddef>

#define BB 4096
#define LL 50
#define NN 50
#define DD 128
#define PK 136                    // padded row stride (elements) -> 272B = 17*16: LDSM-aligned, conflict-free
#define TILE4 2176                // float4s per bf16 tile image (128*PK*2/16)

// ---- main-kernel smem layout (byte offsets) ----
#define WS_HI 0
#define WS_LO 34816
#define A_HI  69632
#define A_LO  104448
#define AUX   139264
#define AUX_CNT   (AUX + 0)       // int[2][64]
#define AUX_WA    (AUX + 512)     // float[128]
#define AUX_VNP   (AUX + 1024)    // float[2][128]
#define AUX_ALPHA (AUX + 2048)    // float[2][64]
#define AUX_PART  (AUX + 2560)    // float[128][8]
#define SMEM_TOTAL (AUX + 6656)   // 145920

__device__ float g_vnp[BB * DD];
__device__ __align__(16) __nv_bfloat16 g_ws_hi[128 * PK];   // [n][k] transposed W_seq, hi
__device__ __align__(16) __nv_bfloat16 g_ws_lo[128 * PK];   // lo

__device__ __forceinline__ uint32_t smem_u32(const void* p) {
    uint32_t a;
    asm("{ .reg .u64 t; cvta.to.shared.u64 t, %1; cvt.u32.u64 %0, t; }" : "=r"(a) : "l"(p));
    return a;
}
__device__ __forceinline__ void ldsm_x4(uint32_t& r0, uint32_t& r1, uint32_t& r2, uint32_t& r3, uint32_t addr) {
    asm volatile("ldmatrix.sync.aligned.m8n8.x4.shared.b16 {%0,%1,%2,%3}, [%4];"
                 : "=r"(r0), "=r"(r1), "=r"(r2), "=r"(r3) : "r"(addr));
}
__device__ __forceinline__ void mma_bf16(float* d, uint32_t a0, uint32_t a1, uint32_t a2, uint32_t a3,
                                         uint32_t b0, uint32_t b1) {
    asm volatile("mma.sync.aligned.m16n8k16.row.col.f32.bf16.bf16.f32 "
                 "{%0,%1,%2,%3}, {%4,%5,%6,%7}, {%8,%9}, {%0,%1,%2,%3};"
                 : "+f"(d[0]), "+f"(d[1]), "+f"(d[2]), "+f"(d[3])
                 : "r"(a0), "r"(a1), "r"(a2), "r"(a3), "r"(b0), "r"(b1));
}
__device__ __forceinline__ float sigf(float z) {
    return 1.0f / (1.0f + __expf(-z));
}

// ============================================================
// Prep: bake W_seq^T into split-bf16 [n][k] images (stride PK)
// ============================================================
__global__ __launch_bounds__(128)
void prep_w_kernel(const float* __restrict__ Ws) {
    const int k = threadIdx.x;    // 0..127
    const int n = blockIdx.x;     // 0..127
    const float w = Ws[k * DD + n];
    const __nv_bfloat16 h = __float2bfloat16(w);
    g_ws_hi[n * PK + k] = h;
    g_ws_lo[n * PK + k] = __float2bfloat16(w - __bfloat162float(h));
}

// ============================================================
// vn kernel (batched): 32 batches/block, W_last staged once.
// Writes v_n to out[0:B*D] and vnp=v_n@W_last+b_seq to g_vnp.
// ============================================================
#define VN_SMEM ((16384 + 128 + 8 * 128) * 4)
__global__ __launch_bounds__(256)
void vn_kernel(
    const int*   __restrict__ seq,
    const int*   __restrict__ mask,
    const float* __restrict__ nodes,
    const float* __restrict__ W_last,
    const float* __restrict__ b_seq,
    float*       __restrict__ out)
{
    extern __shared__ float dsm[];
    float* wl_s = dsm;               // 16384
    float* bs_s = dsm + 16384;       // 128
    float* vnb  = dsm + 16512;       // 8 warps * 128

    const int tid = threadIdx.x, wid = tid >> 5, lane = tid & 31;
    const int b0 = blockIdx.x * 32;

    #pragma unroll
    for (int i = tid; i < 4096; i += 256)
        ((float4*)wl_s)[i] = ((const float4*)W_last)[i];
    if (tid < DD) bs_s[tid] = b_seq[tid];
    __syncthreads();

    for (int r = 0; r < 4; r++) {
        const int b = b0 + wid * 4 + r;
        int cnt = ((lane      < LL) ? mask[b * LL + lane]      : 0)
                + ((lane + 32 < LL) ? mask[b * LL + lane + 32] : 0);
        #pragma unroll
        for (int off = 16; off > 0; off >>= 1)
            cnt += __shfl_xor_sync(0xffffffffu, cnt, off);
        int last = 0;
        if (lane == 0)
            last = seq[b * LL + ((cnt > 0) ? cnt - 1 : LL - 1)];
        last = __shfl_sync(0xffffffffu, last, 0);

        const float4 v = ((const float4*)(nodes + (size_t)b * NN * DD + (size_t)last * DD))[lane];
        ((float4*)(out + (size_t)b * DD))[lane] = v;       // v_n output (exact copy)
        ((float4*)(vnb + wid * 128))[lane] = v;
        __syncwarp();

        float a0 = 0.f, a1 = 0.f, a2 = 0.f, a3 = 0.f;
        const float* vr = vnb + wid * 128;
        #pragma unroll 4
        for (int k = 0; k < 128; k++) {
            const float vk = vr[k];
            const float* wr = wl_s + k * 128 + lane;
            a0 = fmaf(vk, wr[0],  a0);
            a1 = fmaf(vk, wr[32], a1);
            a2 = fmaf(vk, wr[64], a2);
            a3 = fmaf(vk, wr[96], a3);
        }
        float* gv = g_vnp + (size_t)b * DD + lane;
        gv[0]  = a0 + bs_s[lane];
        gv[32] = a1 + bs_s[lane + 32];
        gv[64] = a2 + bs_s[lane + 64];
        gv[96] = a3 + bs_s[lane + 96];
        __syncwarp();
    }
}

// ============================================================
// Main: 2 batches/CTA, mma.sync split-bf16 GEMM + fused epilogue
// ============================================================
__global__ __launch_bounds__(256, 1)
void session_mma_kernel(
    const int*   __restrict__ seq,
    const int*   __restrict__ mask,
    const float* __restrict__ nodes,
    const float* __restrict__ W_alpha,
    float*       __restrict__ out)
{
    extern __shared__ char smem[];
    const uint32_t sb = smem_u32(smem);
    const int tid = threadIdx.x, wid = tid >> 5, lane = tid & 31;
    const int b0 = 2 * blockIdx.x;

    int*   cnt_s   = (int*)  (smem + AUX_CNT);
    float* wa_s    = (float*)(smem + AUX_WA);
    float* vnp_s   = (float*)(smem + AUX_VNP);
    float* alpha_s = (float*)(smem + AUX_ALPHA);
    float* part    = (float*)(smem + AUX_PART);

    if (tid < 128) { cnt_s[tid] = 0; wa_s[tid] = W_alpha[tid]; }
    __syncthreads();

    if (tid < 2 * LL) {
        const int bl = tid / LL, pos = tid % LL;
        const int g = (b0 + bl) * LL + pos;
        if (mask[g]) atomicAdd(&cnt_s[bl * 64 + seq[g]], 1);
    }

    // vnp for both batches (from vn_kernel)
    vnp_s[tid] = g_vnp[(size_t)(b0 + (tid >> 7)) * DD + (tid & 127)];

    // stage W_seq split images (verbatim copies)
    #pragma unroll
    for (int i = tid; i < TILE4; i += 256) {
        ((float4*)(smem + WS_HI))[i] = ((const float4*)g_ws_hi)[i];
        ((float4*)(smem + WS_LO))[i] = ((const float4*)g_ws_lo)[i];
    }
    // zero pad A rows 100..127 (disjoint from node rows; byte 100*272=27200 -> f4 idx 1700)
    for (int i = 1700 + tid; i < TILE4; i += 256) {
        ((float4*)(smem + A_HI))[i] = make_float4(0.f, 0.f, 0.f, 0.f);
        ((float4*)(smem + A_LO))[i] = make_float4(0.f, 0.f, 0.f, 0.f);
    }
    // nodes (rows 0..99) -> split bf16 into A tiles, stride PK
    {
        const float4* nv = (const float4*)(nodes + (size_t)b0 * NN * DD);
        #pragma unroll 4
        for (int i = tid; i < 3200; i += 256) {
            const float4 x = nv[i];
            const int e = i * 4, row = e >> 7, k = e & 127;
            const __nv_bfloat16 h0 = __float2bfloat16(x.x);
            const __nv_bfloat16 h1 = __float2bfloat16(x.y);
            const __nv_bfloat16 h2 = __float2bfloat16(x.z);
            const __nv_bfloat16 h3 = __float2bfloat16(x.w);
            const __nv_bfloat16 l0 = __float2bfloat16(x.x - __bfloat162float(h0));
            const __nv_bfloat16 l1 = __float2bfloat16(x.y - __bfloat162float(h1));
            const __nv_bfloat16 l2 = __float2bfloat16(x.z - __bfloat162float(h2));
            const __nv_bfloat16 l3 = __float2bfloat16(x.w - __bfloat162float(h3));
            uint2 vh, vl;
            vh.x = (uint32_t)__bfloat16_as_ushort(h0) | ((uint32_t)__bfloat16_as_ushort(h1) << 16);
            vh.y = (uint32_t)__bfloat16_as_ushort(h2) | ((uint32_t)__bfloat16_as_ushort(h3) << 16);
            vl.x = (uint32_t)__bfloat16_as_ushort(l0) | ((uint32_t)__bfloat16_as_ushort(l1) << 16);
            vl.y = (uint32_t)__bfloat16_as_ushort(l2) | ((uint32_t)__bfloat16_as_ushort(l3) << 16);
            const uint32_t off = (uint32_t)row * (PK * 2) + (uint32_t)k * 2;  // 8B aligned
            *(uint2*)(smem + A_HI + off) = vh;
            *(uint2*)(smem + A_LO + off) = vl;
        }
    }
    __syncthreads();

    // ---- mma.sync mainloop: 7 m-tiles x 2 n-tiles per warp, 8 k-steps, 3 passes ----
    const int nbase = wid * 16;
    float d[7][2][4];
    #pragma unroll
    for (int mt = 0; mt < 7; mt++)
        #pragma unroll
        for (int nt = 0; nt < 2; nt++)
            #pragma unroll
            for (int e = 0; e < 4; e++) d[mt][nt][e] = 0.f;

    const int lr  = lane & 7;
    const int g8  = (lane >> 3) & 1;
    const int g16 = lane >> 4;
    const uint32_t aRow = (uint32_t)(8 * g8 + lr) * (PK * 2) + (uint32_t)g16 * 16;
    const uint32_t bRow = (uint32_t)(nbase + 8 * g16 + lr) * (PK * 2) + (uint32_t)g8 * 16;

    #pragma unroll
    for (int pass = 0; pass < 3; pass++) {
        const uint32_t Ab = sb + ((pass == 2) ? A_LO : A_HI);
        const uint32_t Bb = sb + ((pass == 1) ? WS_LO : WS_HI);
        #pragma unroll
        for (int ks = 0; ks < 8; ks++) {
            const uint32_t kb = (uint32_t)ks * 32;   // 16 elems * 2B
            uint32_t w0, w1, w2, w3;
            ldsm_x4(w0, w1, w2, w3, Bb + bRow + kb);
            #pragma unroll
            for (int mt = 0; mt < 7; mt++) {
                uint32_t a0, a1, a2, a3;
                ldsm_x4(a0, a1, a2, a3, Ab + aRow + (uint32_t)mt * (16 * PK * 2) + kb);
                mma_bf16(d[mt][0], a0, a1, a2, a3, w0, w1);
                mma_bf16(d[mt][1], a0, a1, a2, a3, w2, w3);
            }
        }
    }

    // ---- epilogue: sigmoid, scale by W_alpha, row-wise reduce ----
    {
        const int q = lane & 3;
        #pragma unroll
        for (int mt = 0; mt < 7; mt++) {
            const int r0 = 16 * mt + (lane >> 2);
            const int r1 = r0 + 8;
            const float* vp0 = vnp_s + ((r0 < 50) ? 0 : 128);
            const float* vp1 = vnp_s + ((r1 < 50) ? 0 : 128);
            float p0 = 0.f, p1 = 0.f;
            #pragma unroll
            for (int nt = 0; nt < 2; nt++) {
                const int c = nbase + nt * 8 + 2 * q;
                const float wa0 = wa_s[c], wa1 = wa_s[c + 1];
                p0 += sigf(vp0[c] + d[mt][nt][0]) * wa0 + sigf(vp0[c + 1] + d[mt][nt][1]) * wa1;
                p1 += sigf(vp1[c] + d[mt][nt][2]) * wa0 + sigf(vp1[c + 1] + d[mt][nt][3]) * wa1;
            }
            p0 += __shfl_xor_sync(0xffffffffu, p0, 1);
            p0 += __shfl_xor_sync(0xffffffffu, p0, 2);
            p1 += __shfl_xor_sync(0xffffffffu, p1, 1);
            p1 += __shfl_xor_sync(0xffffffffu, p1, 2);
            if ((lane & 3) == 0) {
                part[r0 * 8 + wid] = p0;
                part[r1 * 8 + wid] = p1;
            }
        }
    }
    __syncthreads();

    // alpha[n] (x masked multiplicity), rows 0..99
    if (tid < 100) {
        float a = 0.f;
        #pragma unroll
        for (int w = 0; w < 8; w++) a += part[tid * 8 + w];
        const int bt = (tid < 50) ? 0 : 1;
        const int n  = tid - bt * 50;
        alpha_s[bt * 64 + n] = a * (float)cnt_s[bt * 64 + n];
    }
    __syncthreads();

    // session_graph (nodes re-read, L2-hot)
    {
        const int bl = tid >> 7, c = tid & 127;
        const int b = b0 + bl;
        const float* nb = nodes + (size_t)b * NN * DD;
        const float* as = alpha_s + bl * 64;
        float sg = 0.f;
        #pragma unroll
        for (int n = 0; n < NN; n++)
            sg = fmaf(as[n], nb[n * DD + c], sg);
        out[(size_t)BB * DD + (size_t)b * DD + c] = sg;
    }
}

extern "C" void kernel_launch(void* const* d_in, const int* in_sizes, int n_in,
                              void* d_out, int out_size) {
    const int*   seq     = (const int*)  d_in[0];
    const int*   mask    = (const int*)  d_in[1];
    const float* nodes   = (const float*)d_in[2];
    // d_in[3] = batch_size scalar (compile-time constants used)
    const float* W_last  = (const float*)d_in[4];
    const float* W_seq   = (const float*)d_in[5];
    const float* b_seq   = (const float*)d_in[6];
    const float* W_alpha = (const float*)d_in[7];
    float* out = (float*)d_out;

    prep_w_kernel<<<128, 128>>>(W_seq);

    cudaFuncSetAttribute(vn_kernel, cudaFuncAttributeMaxDynamicSharedMemorySize, VN_SMEM);
    vn_kernel<<<128, 256, VN_SMEM>>>(seq, mask, nodes, W_last, b_seq, out);

    cudaFuncSetAttribute(session_mma_kernel,
                         cudaFuncAttributeMaxDynamicSharedMemorySize, SMEM_TOTAL);
    session_mma_kernel<<<2048, 256, SMEM_TOTAL>>>(seq, mask, nodes, W_alpha, out);
}

// round 12
// speedup vs baseline: 1.7837x; 1.0769x over previous
#include <cuda_runtime.h>
#include <cuda_bf16.h>
#include <cstdint>
#include <cstddef>

#define BB 4096
#define LL 50
#define NN 50
#define DD 128
#define PK 136                    // padded row stride (elements) -> 272B = 17*16: LDSM-aligned, conflict-free
#define TILE4 2176                // float4s per bf16 tile image (128*PK*2/16)

// ---- main-kernel smem layout (byte offsets) ----
#define WS_HI 0
#define WS_LO 34816
#define A_HI  69632
#define A_LO  104448
#define AUX   139264
#define AUX_CNT   (AUX + 0)       // int[4][64]
#define AUX_WA    (AUX + 1024)    // float[128]
#define AUX_VNP   (AUX + 1536)    // float[4][128]
#define AUX_ALPHA (AUX + 3584)    // float[4][64]
#define AUX_PART  (AUX + 4608)    // float[128][8]
#define SMEM_TOTAL (AUX + 8704)   // 147968

__device__ float g_vnp[BB * DD];
__device__ __align__(16) __nv_bfloat16 g_ws_hi[128 * PK];   // [n][k] transposed W_seq, hi
__device__ __align__(16) __nv_bfloat16 g_ws_lo[128 * PK];   // lo

__device__ __forceinline__ uint32_t smem_u32(const void* p) {
    uint32_t a;
    asm("{ .reg .u64 t; cvta.to.shared.u64 t, %1; cvt.u32.u64 %0, t; }" : "=r"(a) : "l"(p));
    return a;
}
__device__ __forceinline__ void ldsm_x4(uint32_t& r0, uint32_t& r1, uint32_t& r2, uint32_t& r3, uint32_t addr) {
    asm volatile("ldmatrix.sync.aligned.m8n8.x4.shared.b16 {%0,%1,%2,%3}, [%4];"
                 : "=r"(r0), "=r"(r1), "=r"(r2), "=r"(r3) : "r"(addr));
}
__device__ __forceinline__ void mma_bf16(float* d, uint32_t a0, uint32_t a1, uint32_t a2, uint32_t a3,
                                         uint32_t b0, uint32_t b1) {
    asm volatile("mma.sync.aligned.m16n8k16.row.col.f32.bf16.bf16.f32 "
                 "{%0,%1,%2,%3}, {%4,%5,%6,%7}, {%8,%9}, {%0,%1,%2,%3};"
                 : "+f"(d[0]), "+f"(d[1]), "+f"(d[2]), "+f"(d[3])
                 : "r"(a0), "r"(a1), "r"(a2), "r"(a3), "r"(b0), "r"(b1));
}
__device__ __forceinline__ float sigf(float z) {
    return 1.0f / (1.0f + __expf(-z));
}
__device__ __forceinline__ void cp_async16(uint32_t saddr, const void* gaddr) {
    asm volatile("cp.async.cg.shared.global [%0], [%1], 16;" :: "r"(saddr), "l"(gaddr));
}

// ============================================================
// Combo kernel: blocks 0..127 -> vn (32 batches each, W_last staged);
//               blocks 128..159 -> prep W_seq split images.
// ============================================================
#define VN_SMEM ((16384 + 128 + 8 * 128) * 4)
__global__ __launch_bounds__(256)
void combo_kernel(
    const int*   __restrict__ seq,
    const int*   __restrict__ mask,
    const float* __restrict__ nodes,
    const float* __restrict__ W_last,
    const float* __restrict__ W_seq,
    const float* __restrict__ b_seq,
    float*       __restrict__ out)
{
    extern __shared__ float dsm[];
    const int tid = threadIdx.x, wid = tid >> 5, lane = tid & 31;

    if (blockIdx.x >= 128) {
        // ---- prep: bake W_seq^T split-bf16 [n][k], stride PK ----
        const int base = (blockIdx.x - 128) * 512 + tid * 2;
        #pragma unroll
        for (int j = 0; j < 2; j++) {
            const int t = base + j;          // 0..16383
            const int k = t & 127, n = t >> 7;
            const float w = W_seq[k * DD + n];
            const __nv_bfloat16 h = __float2bfloat16(w);
            g_ws_hi[n * PK + k] = h;
            g_ws_lo[n * PK + k] = __float2bfloat16(w - __bfloat162float(h));
        }
        return;
    }

    // ---- vn: 32 batches per block ----
    float* wl_s = dsm;               // 16384
    float* bs_s = dsm + 16384;       // 128
    float* vnb  = dsm + 16512;       // 8 warps * 128
    const int b0 = blockIdx.x * 32;

    #pragma unroll
    for (int i = tid; i < 4096; i += 256)
        ((float4*)wl_s)[i] = ((const float4*)W_last)[i];
    if (tid < DD) bs_s[tid] = b_seq[tid];
    __syncthreads();

    for (int r = 0; r < 4; r++) {
        const int b = b0 + wid * 4 + r;
        int cnt = ((lane      < LL) ? mask[b * LL + lane]      : 0)
                + ((lane + 32 < LL) ? mask[b * LL + lane + 32] : 0);
        #pragma unroll
        for (int off = 16; off > 0; off >>= 1)
            cnt += __shfl_xor_sync(0xffffffffu, cnt, off);
        int last = 0;
        if (lane == 0)
            last = seq[b * LL + ((cnt > 0) ? cnt - 1 : LL - 1)];
        last = __shfl_sync(0xffffffffu, last, 0);

        const float4 v = ((const float4*)(nodes + (size_t)b * NN * DD + (size_t)last * DD))[lane];
        ((float4*)(out + (size_t)b * DD))[lane] = v;       // v_n output (exact copy)
        ((float4*)(vnb + wid * 128))[lane] = v;
        __syncwarp();

        float a0 = 0.f, a1 = 0.f, a2 = 0.f, a3 = 0.f;
        const float* vr = vnb + wid * 128;
        #pragma unroll 4
        for (int k = 0; k < 128; k++) {
            const float vk = vr[k];
            const float* wr = wl_s + k * 128 + lane;
            a0 = fmaf(vk, wr[0],  a0);
            a1 = fmaf(vk, wr[32], a1);
            a2 = fmaf(vk, wr[64], a2);
            a3 = fmaf(vk, wr[96], a3);
        }
        float* gv = g_vnp + (size_t)b * DD + lane;
        gv[0]  = a0 + bs_s[lane];
        gv[32] = a1 + bs_s[lane + 32];
        gv[64] = a2 + bs_s[lane + 64];
        gv[96] = a3 + bs_s[lane + 96];
        __syncwarp();
    }
}

// ============================================================
// Main: 4 batches/CTA (two A-phases), W staged once via cp.async,
// mma.sync split-bf16 GEMM + fused epilogue
// ============================================================
__global__ __launch_bounds__(256, 1)
void session_mma_kernel(
    const int*   __restrict__ seq,
    const int*   __restrict__ mask,
    const float* __restrict__ nodes,
    const float* __restrict__ W_alpha,
    float*       __restrict__ out)
{
    extern __shared__ char smem[];
    const uint32_t sb = smem_u32(smem);
    const int tid = threadIdx.x, wid = tid >> 5, lane = tid & 31;
    const int b0 = 4 * blockIdx.x;

    int*   cnt_s   = (int*)  (smem + AUX_CNT);
    float* wa_s    = (float*)(smem + AUX_WA);
    float* vnp_s   = (float*)(smem + AUX_VNP);
    float* alpha_s = (float*)(smem + AUX_ALPHA);
    float* part    = (float*)(smem + AUX_PART);

    // ---- kick off W image staging via cp.async (waited before phase-0 sync) ----
    {
        for (int i = tid; i < TILE4; i += 256) {
            cp_async16(sb + WS_HI + i * 16, (const char*)g_ws_hi + i * 16);
            cp_async16(sb + WS_LO + i * 16, (const char*)g_ws_lo + i * 16);
        }
        asm volatile("cp.async.commit_group;");
    }

    cnt_s[tid] = 0;                       // 4*64 = 256 ints
    if (tid < 128) wa_s[tid] = W_alpha[tid];
    __syncthreads();

    // masked counts for 4 batches
    if (tid < 4 * LL) {
        const int bl = tid / LL, pos = tid % LL;
        const int g = (b0 + bl) * LL + pos;
        if (mask[g]) atomicAdd(&cnt_s[bl * 64 + seq[g]], 1);
    }
    // vnp for 4 batches (from combo kernel)
    #pragma unroll
    for (int j = 0; j < 2; j++) {
        const int i = tid + 256 * j;      // 0..511
        vnp_s[i] = g_vnp[(size_t)(b0 + (i >> 7)) * DD + (i & 127)];
    }
    // zero pad A rows 100..127 once (never overwritten by node conversion)
    for (int i = 1700 + tid; i < TILE4; i += 256) {
        ((float4*)(smem + A_HI))[i] = make_float4(0.f, 0.f, 0.f, 0.f);
        ((float4*)(smem + A_LO))[i] = make_float4(0.f, 0.f, 0.f, 0.f);
    }

    const int lr  = lane & 7;
    const int g8  = (lane >> 3) & 1;
    const int g16 = lane >> 4;
    const int nbase = wid * 16;
    const uint32_t aRow = (uint32_t)(8 * g8 + lr) * (PK * 2) + (uint32_t)g16 * 16;
    const uint32_t bRow = (uint32_t)(nbase + 8 * g16 + lr) * (PK * 2) + (uint32_t)g8 * 16;

    #pragma unroll 1
    for (int ph = 0; ph < 2; ph++) {
        const int pb = b0 + 2 * ph;

        // ---- stage A: nodes (rows 0..99) -> split bf16, stride PK ----
        {
            const float4* nv = (const float4*)(nodes + (size_t)pb * NN * DD);
            #pragma unroll 4
            for (int i = tid; i < 3200; i += 256) {
                const float4 x = nv[i];
                const int e = i * 4, row = e >> 7, k = e & 127;
                const __nv_bfloat16 h0 = __float2bfloat16(x.x);
                const __nv_bfloat16 h1 = __float2bfloat16(x.y);
                const __nv_bfloat16 h2 = __float2bfloat16(x.z);
                const __nv_bfloat16 h3 = __float2bfloat16(x.w);
                const __nv_bfloat16 l0 = __float2bfloat16(x.x - __bfloat162float(h0));
                const __nv_bfloat16 l1 = __float2bfloat16(x.y - __bfloat162float(h1));
                const __nv_bfloat16 l2 = __float2bfloat16(x.z - __bfloat162float(h2));
                const __nv_bfloat16 l3 = __float2bfloat16(x.w - __bfloat162float(h3));
                uint2 vh, vl;
                vh.x = (uint32_t)__bfloat16_as_ushort(h0) | ((uint32_t)__bfloat16_as_ushort(h1) << 16);
                vh.y = (uint32_t)__bfloat16_as_ushort(h2) | ((uint32_t)__bfloat16_as_ushort(h3) << 16);
                vl.x = (uint32_t)__bfloat16_as_ushort(l0) | ((uint32_t)__bfloat16_as_ushort(l1) << 16);
                vl.y = (uint32_t)__bfloat16_as_ushort(l2) | ((uint32_t)__bfloat16_as_ushort(l3) << 16);
                const uint32_t off = (uint32_t)row * (PK * 2) + (uint32_t)k * 2;  // 8B aligned
                *(uint2*)(smem + A_HI + off) = vh;
                *(uint2*)(smem + A_LO + off) = vl;
            }
        }
        if (ph == 0) asm volatile("cp.async.wait_group 0;" ::: "memory");
        __syncthreads();

        // ---- mma.sync mainloop: 7 m-tiles x 2 n-tiles per warp, 8 k-steps, 3 passes ----
        float d[7][2][4];
        #pragma unroll
        for (int mt = 0; mt < 7; mt++)
            #pragma unroll
            for (int nt = 0; nt < 2; nt++)
                #pragma unroll
                for (int e = 0; e < 4; e++) d[mt][nt][e] = 0.f;

        #pragma unroll
        for (int pass = 0; pass < 3; pass++) {
            const uint32_t Ab = sb + ((pass == 2) ? A_LO : A_HI);
            const uint32_t Bb = sb + ((pass == 1) ? WS_LO : WS_HI);
            #pragma unroll
            for (int ks = 0; ks < 8; ks++) {
                const uint32_t kb = (uint32_t)ks * 32;   // 16 elems * 2B
                uint32_t w0, w1, w2, w3;
                ldsm_x4(w0, w1, w2, w3, Bb + bRow + kb);
                #pragma unroll
                for (int mt = 0; mt < 7; mt++) {
                    uint32_t a0, a1, a2, a3;
                    ldsm_x4(a0, a1, a2, a3, Ab + aRow + (uint32_t)mt * (16 * PK * 2) + kb);
                    mma_bf16(d[mt][0], a0, a1, a2, a3, w0, w1);
                    mma_bf16(d[mt][1], a0, a1, a2, a3, w2, w3);
                }
            }
        }

        // ---- epilogue: sigmoid, scale by W_alpha, row-wise reduce ----
        {
            const int q = lane & 3;
            #pragma unroll
            for (int mt = 0; mt < 7; mt++) {
                const int r0 = 16 * mt + (lane >> 2);
                const int r1 = r0 + 8;
                const float* vp0 = vnp_s + (2 * ph + ((r0 < 50) ? 0 : 1)) * 128;
                const float* vp1 = vnp_s + (2 * ph + ((r1 < 50) ? 0 : 1)) * 128;
                float p0 = 0.f, p1 = 0.f;
                #pragma unroll
                for (int nt = 0; nt < 2; nt++) {
                    const int c = nbase + nt * 8 + 2 * q;
                    const float wa0 = wa_s[c], wa1 = wa_s[c + 1];
                    p0 += sigf(vp0[c] + d[mt][nt][0]) * wa0 + sigf(vp0[c + 1] + d[mt][nt][1]) * wa1;
                    p1 += sigf(vp1[c] + d[mt][nt][2]) * wa0 + sigf(vp1[c + 1] + d[mt][nt][3]) * wa1;
                }
                p0 += __shfl_xor_sync(0xffffffffu, p0, 1);
                p0 += __shfl_xor_sync(0xffffffffu, p0, 2);
                p1 += __shfl_xor_sync(0xffffffffu, p1, 1);
                p1 += __shfl_xor_sync(0xffffffffu, p1, 2);
                if ((lane & 3) == 0) {
                    part[r0 * 8 + wid] = p0;
                    part[r1 * 8 + wid] = p1;
                }
            }
        }
        __syncthreads();

        // alpha[n] (x masked multiplicity), rows 0..99 of this phase
        if (tid < 100) {
            float a = 0.f;
            #pragma unroll
            for (int w = 0; w < 8; w++) a += part[tid * 8 + w];
            const int bt = (tid < 50) ? 0 : 1;
            const int n  = tid - bt * 50;
            const int g  = 2 * ph + bt;
            alpha_s[g * 64 + n] = a * (float)cnt_s[g * 64 + n];
        }
        __syncthreads();
    }

    // ---- session_graph for all 4 batches (nodes re-read, L2-hot) ----
    #pragma unroll
    for (int j = 0; j < 2; j++) {
        const int bl = 2 * j + (tid >> 7);
        const int c  = tid & 127;
        const int b  = b0 + bl;
        const float* nb = nodes + (size_t)b * NN * DD;
        const float* as = alpha_s + bl * 64;
        float sg = 0.f;
        #pragma unroll
        for (int n = 0; n < NN; n++)
            sg = fmaf(as[n], nb[n * DD + c], sg);
        out[(size_t)BB * DD + (size_t)b * DD + c] = sg;
    }
}

extern "C" void kernel_launch(void* const* d_in, const int* in_sizes, int n_in,
                              void* d_out, int out_size) {
    const int*   seq     = (const int*)  d_in[0];
    const int*   mask    = (const int*)  d_in[1];
    const float* nodes   = (const float*)d_in[2];
    // d_in[3] = batch_size scalar (compile-time constants used)
    const float* W_last  = (const float*)d_in[4];
    const float* W_seq   = (const float*)d_in[5];
    const float* b_seq   = (const float*)d_in[6];
    const float* W_alpha = (const float*)d_in[7];
    float* out = (float*)d_out;

    cudaFuncSetAttribute(combo_kernel, cudaFuncAttributeMaxDynamicSharedMemorySize, VN_SMEM);
    combo_kernel<<<160, 256, VN_SMEM>>>(seq, mask, nodes, W_last, W_seq, b_seq, out);

    cudaFuncSetAttribute(session_mma_kernel,
                         cudaFuncAttributeMaxDynamicSharedMemorySize, SMEM_TOTAL);
    session_mma_kernel<<<1024, 256, SMEM_TOTAL>>>(seq, mask, nodes, W_alpha, out);
}